// round 3
// baseline (speedup 1.0000x reference)
#include <cuda_runtime.h>

// PercolationQ: per-patch occupancy fraction -> threshold -> mean over patches.
// Pure HBM-bound streaming reduction over three 50 MB fp32 tensors.
//
// Layout:
//   x4 : [3, 64, 4096, 4, 4]   row (c,b) = 65536 contiguous floats, patch = 16 floats
//   x8 : [3, 64, 1024, 8, 8]   row = 65536 floats, patch = 64 floats
//   x16: [3, 64,  256,16,16]   row = 65536 floats, patch = 256 floats
// Output: [q4(3,64), q8(3,64), q16(3,64)] concatenated = 576 floats.
//
// One fused kernel, 2304 blocks x 256 threads, every block streams exactly
// 64 KB (balanced waves). Deterministic per-block partial counts -> __device__
// scratch (no atomics, no memset), tiny finalize kernel divides by P.

#define PERC_THR 0.59275f

// 192 rows * 4 blocks-per-row for each tensor
__device__ int g_part4[768];
__device__ int g_part8[768];
__device__ int g_part16[768];

__device__ __forceinline__ float red4(float4 a) {
    return (a.x + a.y) + (a.z + a.w);
}

// Returns valid total only on threadIdx.x == 0.
__device__ __forceinline__ int block_reduce_count(int c, int* sh) {
    c = __reduce_add_sync(0xffffffffu, c);
    int warp = threadIdx.x >> 5;
    if ((threadIdx.x & 31) == 0) sh[warp] = c;
    __syncthreads();
    if (threadIdx.x == 0) {
        int s = 0;
#pragma unroll
        for (int i = 0; i < 8; i++) s += sh[i];
        return s;
    }
    return 0;
}

__global__ void __launch_bounds__(256, 1)
perc_kernel(const float* __restrict__ x4,
            const float* __restrict__ x8,
            const float* __restrict__ x16) {
    __shared__ int sh[8];
    const int bid = blockIdx.x;
    const int tid = threadIdx.x;

    if (bid < 768) {
        // ---- x4: row = bid/4, 1024 patches per block, 4 patches per thread ----
        const int row = bid >> 2;
        const int blk = bid & 3;
        const float4* base =
            (const float4*)(x4 + (size_t)row * 65536) + (size_t)blk * 1024 * 4;
        int cnt = 0;
#pragma unroll
        for (int k = 0; k < 4; k++) {
            const float4* p = base + (size_t)(k * 256 + tid) * 4;
            float4 a0 = p[0], a1 = p[1], a2 = p[2], a3 = p[3];
            float s = (red4(a0) + red4(a1)) + (red4(a2) + red4(a3));
            cnt += (s * 0.0625f >= PERC_THR) ? 1 : 0;
        }
        int total = block_reduce_count(cnt, sh);
        if (tid == 0) g_part4[bid] = total;
    } else if (bid < 1536) {
        // ---- x8: 256 patches per block, 1 patch per thread (16 float4) ----
        const int b = bid - 768;
        const int row = b >> 2;
        const int blk = b & 3;
        const float4* p = (const float4*)(x8 + (size_t)row * 65536) +
                          ((size_t)blk * 256 + tid) * 16;
        float4 acc = make_float4(0.f, 0.f, 0.f, 0.f);
#pragma unroll
        for (int i = 0; i < 16; i++) {
            float4 v = p[i];
            acc.x += v.x; acc.y += v.y; acc.z += v.z; acc.w += v.w;
        }
        float s = red4(acc);
        int cnt = (s * 0.015625f >= PERC_THR) ? 1 : 0;
        int total = block_reduce_count(cnt, sh);
        if (tid == 0) g_part8[b] = total;
    } else {
        // ---- x16: 64 patches per block, 4 threads per patch (16 float4 each) ----
        const int b = bid - 1536;
        const int row = b >> 2;
        const int blk = b & 3;
        const int patch = blk * 64 + (tid >> 2);
        const int sub = tid & 3;
        const float4* p = (const float4*)(x16 + (size_t)row * 65536) +
                          (size_t)patch * 64 + (size_t)sub * 16;
        float4 acc = make_float4(0.f, 0.f, 0.f, 0.f);
#pragma unroll
        for (int i = 0; i < 16; i++) {
            float4 v = p[i];
            acc.x += v.x; acc.y += v.y; acc.z += v.z; acc.w += v.w;
        }
        float s = red4(acc);
        // combine the 4 sub-sums of this patch (lanes 4g..4g+3)
        s += __shfl_xor_sync(0xffffffffu, s, 1);
        s += __shfl_xor_sync(0xffffffffu, s, 2);
        int cnt = (sub == 0 && (s * 0.00390625f >= PERC_THR)) ? 1 : 0;
        int total = block_reduce_count(cnt, sh);
        if (tid == 0) g_part16[b] = total;
    }
}

__global__ void perc_finalize(float* __restrict__ out) {
    const int t = threadIdx.x;
    if (t >= 576) return;
    const int tensor = t / 192;   // 0: x4, 1: x8, 2: x16
    const int row = t % 192;
    const int* part = (tensor == 0) ? g_part4 : (tensor == 1) ? g_part8 : g_part16;
    int c = part[row * 4 + 0] + part[row * 4 + 1] +
            part[row * 4 + 2] + part[row * 4 + 3];
    const float invP = (tensor == 0) ? (1.0f / 4096.0f)
                     : (tensor == 1) ? (1.0f / 1024.0f)
                                     : (1.0f / 256.0f);
    out[t] = (float)c * invP;
}

extern "C" void kernel_launch(void* const* d_in, const int* in_sizes, int n_in,
                              void* d_out, int out_size) {
    const float* x4  = (const float*)d_in[0];
    const float* x8  = (const float*)d_in[1];
    const float* x16 = (const float*)d_in[2];
    float* out = (float*)d_out;

    perc_kernel<<<2304, 256>>>(x4, x8, x16);
    perc_finalize<<<1, 576>>>(out);
}